// round 3
// baseline (speedup 1.0000x reference)
#include <cuda_runtime.h>
#include <cstdint>

// NeRF positional encoding:
//   x:   [rows, 4]   float32   (rows = 64*1024)
//   out: [rows, 768] float32
// out[row, k*64 + L*8 + 2c + s] = (s==0 ? sin : cos)(2^L * pi * x[row,c])
//
// R2: direct STG.256 (st.global.v8.f32, sm_100a+/sm_103a) — halve store
// instruction count and L1tex wavefront pressure vs R0's STG.128, no smem.
// One warp per row. Lane layout:
//   g    = lane & 7  -> frequency L (owns the 8-float group {sin,cos}x4 coords)
//   slot = lane >> 3 -> repetition phase (0..3); 3 iterations cover 12 reps
// Each warp store instruction writes 32 lanes x 32B = 1024B contiguous.

__global__ void __launch_bounds__(256)
nerf_pe_v8_kernel(const float4* __restrict__ x, float* __restrict__ out, int rows) {
    const int warpid = threadIdx.x >> 5;       // one warp per row
    const int lane   = threadIdx.x & 31;
    const int row    = blockIdx.x * 8 + warpid;
    if (row >= rows) return;

    // Broadcast 16B load of this row's 4 coords
    const float4 xv = __ldg(&x[row]);

    const int g    = lane & 7;                 // frequency index L
    const int slot = lane >> 3;                // rep phase 0..3

    // 2^L * pi: exact power-of-two scaling of f32 pi, matches reference
    const float f = 3.14159265358979323846f * (float)(1 << g);

    float s0, c0, s1, c1, s2, c2, s3, c3;
    sincosf(f * xv.x, &s0, &c0);
    sincosf(f * xv.y, &s1, &c1);
    sincosf(f * xv.z, &s2, &c2);
    sincosf(f * xv.w, &s3, &c3);

    // Group g of rep r lives at floats [r*64 + g*8, r*64 + g*8 + 8)
    float* o = out + (size_t)row * 768 + slot * 64 + g * 8;
    #pragma unroll
    for (int r = 0; r < 3; ++r) {
        // reps slot, slot+4, slot+8  (stride 4*64 floats = 1024B per warp step)
        asm volatile(
            "st.global.v8.f32 [%0], {%1,%2,%3,%4,%5,%6,%7,%8};"
            :: "l"(o + r * 256),
               "f"(s0), "f"(c0), "f"(s1), "f"(c1),
               "f"(s2), "f"(c2), "f"(s3), "f"(c3)
            : "memory");
    }
}

extern "C" void kernel_launch(void* const* d_in, const int* in_sizes, int n_in,
                              void* d_out, int out_size) {
    const float4* x = (const float4*)d_in[0];
    float* out = (float*)d_out;
    const int rows = in_sizes[0] / 4;          // [rows, 4] coords

    const int blocks = (rows + 7) / 8;         // 8 rows (warps) per block
    nerf_pe_v8_kernel<<<blocks, 256>>>(x, out, rows);
}